// round 1
// baseline (speedup 1.0000x reference)
#include <cuda_runtime.h>
#include <math.h>

#define BATCH 8
#define DIM   512   // IN_DIM == OUT_DIM
#define HW    4096  // 64*64
#define IDIM  256   // INTER_DIM

// ---------------- device scratch (static; no allocations) ----------------
__device__ float g_Q[(size_t)BATCH * HW * IDIM];        // normalized phi, [b][n][i]
__device__ float g_K[(size_t)BATCH * HW * IDIM];        // normalized theta
__device__ float g_S[(size_t)BATCH * HW * HW];          // scores / softmax (512 MB)
__device__ float g_M[(size_t)BATCH * DIM * HW];         // sim @ feat (transposed) [b][c][n]

// ---------------- k1: phi/theta projection GEMM ----------------
// phiT[i][n] = sum_c phi_w[i][c] * F[b][c][n]; we store as Q[b][n][i] row-major.
// Tile: 64 n x 64 i, BK=32 over c. Computes BOTH phi and theta reusing the F tile.
__global__ void __launch_bounds__(256) k1_project(const float* __restrict__ F,
                                                  const float* __restrict__ Wp,
                                                  const float* __restrict__ Wt) {
    __shared__ float sF[32][64];     // [c][n]
    __shared__ float sP[64][33];     // [i][c] padded
    __shared__ float sT[64][33];

    int b  = blockIdx.z;
    int n0 = blockIdx.x * 64;
    int i0 = blockIdx.y * 64;
    const float* Fb = F + (size_t)b * DIM * HW;

    int tid = threadIdx.x;
    int tx = tid & 15, ty = tid >> 4;

    float accP[4][4]; float accT[4][4];
    #pragma unroll
    for (int u = 0; u < 4; u++)
        #pragma unroll
        for (int v = 0; v < 4; v++) { accP[u][v] = 0.f; accT[u][v] = 0.f; }

    for (int c0 = 0; c0 < DIM; c0 += 32) {
        #pragma unroll
        for (int t = 0; t < 8; t++) {
            int l = tid + t * 256;
            int r = l >> 6, col = l & 63;
            sF[r][col] = Fb[(size_t)(c0 + r) * HW + n0 + col];
        }
        #pragma unroll
        for (int t = 0; t < 8; t++) {
            int l = tid + t * 256;
            int r = l >> 5, cc = l & 31;
            sP[r][cc] = Wp[(size_t)(i0 + r) * DIM + c0 + cc];
            sT[r][cc] = Wt[(size_t)(i0 + r) * DIM + c0 + cc];
        }
        __syncthreads();
        #pragma unroll
        for (int kk = 0; kk < 32; kk++) {
            float fr[4], pr[4], tr[4];
            #pragma unroll
            for (int u = 0; u < 4; u++) fr[u] = sF[kk][ty * 4 + u];
            #pragma unroll
            for (int v = 0; v < 4; v++) { pr[v] = sP[tx * 4 + v][kk]; tr[v] = sT[tx * 4 + v][kk]; }
            #pragma unroll
            for (int u = 0; u < 4; u++)
                #pragma unroll
                for (int v = 0; v < 4; v++) {
                    accP[u][v] += fr[u] * pr[v];
                    accT[u][v] += fr[u] * tr[v];
                }
        }
        __syncthreads();
    }

    size_t base = ((size_t)b * HW) * IDIM;
    #pragma unroll
    for (int u = 0; u < 4; u++) {
        size_t nrow = base + (size_t)(n0 + ty * 4 + u) * IDIM + i0 + tx * 4;
        #pragma unroll
        for (int v = 0; v < 4; v++) {
            g_Q[nrow + v] = accP[u][v];
            g_K[nrow + v] = accT[u][v];
        }
    }
}

// ---------------- k1b: row L2-normalize Q and K ----------------
__global__ void __launch_bounds__(256) k1b_normalize() {
    size_t row = blockIdx.x;            // b*HW + n
    float* q = g_Q + row * IDIM;
    float* k = g_K + row * IDIM;
    int t = threadIdx.x;                // 256 == IDIM
    float qv = q[t], kv = k[t];
    float sq = qv * qv, sk = kv * kv;
    #pragma unroll
    for (int o = 16; o > 0; o >>= 1) {
        sq += __shfl_xor_sync(0xffffffffu, sq, o);
        sk += __shfl_xor_sync(0xffffffffu, sk, o);
    }
    __shared__ float sh[16];
    int w = t >> 5;
    if ((t & 31) == 0) { sh[w] = sq; sh[8 + w] = sk; }
    __syncthreads();
    float tq = 0.f, tk = 0.f;
    #pragma unroll
    for (int i = 0; i < 8; i++) { tq += sh[i]; tk += sh[8 + i]; }
    q[t] = qv / sqrtf(tq);
    k[t] = kv / sqrtf(tk);
}

// ---------------- generic "NT" SGEMM body: C[r][c] = sum_k A[r][k]*B[c][k] ----------------
// 128x128 tile, BK=16, 256 threads, 8x8 per thread. Rows/cols assumed multiples of 128.
__device__ __forceinline__ void gemm_nt_body(const float* __restrict__ Ab,
                                             const float* __restrict__ Bb,
                                             float* __restrict__ Cb,
                                             int Kdim, int Ncols) {
    __shared__ float sA[16][132];
    __shared__ float sB[16][132];

    const float* At = Ab + (size_t)blockIdx.y * 128 * Kdim;
    const float* Bt = Bb + (size_t)blockIdx.x * 128 * Kdim;
    float* Ct = Cb + (size_t)blockIdx.y * 128 * Ncols + (size_t)blockIdx.x * 128;

    int tid = threadIdx.x;
    int tx = tid & 15, ty = tid >> 4;

    float acc[8][8];
    #pragma unroll
    for (int u = 0; u < 8; u++)
        #pragma unroll
        for (int v = 0; v < 8; v++) acc[u][v] = 0.f;

    for (int k0 = 0; k0 < Kdim; k0 += 16) {
        #pragma unroll
        for (int t = 0; t < 2; t++) {
            int l = tid + t * 256;
            int r = l >> 2;
            int kq = (l & 3) * 4;
            float4 va = *reinterpret_cast<const float4*>(At + (size_t)r * Kdim + k0 + kq);
            sA[kq + 0][r] = va.x; sA[kq + 1][r] = va.y; sA[kq + 2][r] = va.z; sA[kq + 3][r] = va.w;
            float4 vb = *reinterpret_cast<const float4*>(Bt + (size_t)r * Kdim + k0 + kq);
            sB[kq + 0][r] = vb.x; sB[kq + 1][r] = vb.y; sB[kq + 2][r] = vb.z; sB[kq + 3][r] = vb.w;
        }
        __syncthreads();
        #pragma unroll
        for (int kk = 0; kk < 16; kk++) {
            float a[8], bb[8];
            #pragma unroll
            for (int u = 0; u < 8; u++) a[u] = sA[kk][ty * 8 + u];
            #pragma unroll
            for (int v = 0; v < 8; v++) bb[v] = sB[kk][tx * 8 + v];
            #pragma unroll
            for (int u = 0; u < 8; u++)
                #pragma unroll
                for (int v = 0; v < 8; v++) acc[u][v] += a[u] * bb[v];
        }
        __syncthreads();
    }
    #pragma unroll
    for (int u = 0; u < 8; u++) {
        float* crow = Ct + (size_t)(ty * 8 + u) * Ncols + tx * 8;
        #pragma unroll
        for (int v = 0; v < 8; v++) crow[v] = acc[u][v];
    }
}

// k2: S[b] = Qn @ Knt   (4096 x 4096, K=256)
__global__ void __launch_bounds__(256) k2_scores() {
    int b = blockIdx.z;
    gemm_nt_body(g_Q + (size_t)b * HW * IDIM,
                 g_K + (size_t)b * HW * IDIM,
                 g_S + (size_t)b * HW * HW, IDIM, HW);
}

// k4: M[b][c][n] = sum_m F[b][c][m] * S[b][n][m]   (512 x 4096, K=4096)
__global__ void __launch_bounds__(256) k4_aggregate(const float* __restrict__ F) {
    int b = blockIdx.z;
    gemm_nt_body(F + (size_t)b * DIM * HW,
                 g_S + (size_t)b * HW * HW,
                 g_M + (size_t)b * DIM * HW, HW, HW);
}

// ---------------- k3: row softmax over g_S ----------------
__global__ void __launch_bounds__(256) k3_softmax() {
    size_t row = blockIdx.x;            // b*HW + n
    float* S = g_S + row * (size_t)HW;
    int t = threadIdx.x;
    float v[16];
    float mx = -3.0e38f;
    #pragma unroll
    for (int i = 0; i < 16; i++) { v[i] = S[t + i * 256]; mx = fmaxf(mx, v[i]); }
    #pragma unroll
    for (int o = 16; o > 0; o >>= 1) mx = fmaxf(mx, __shfl_xor_sync(0xffffffffu, mx, o));
    __shared__ float sh[8];
    int w = t >> 5;
    if ((t & 31) == 0) sh[w] = mx;
    __syncthreads();
    float m = sh[0];
    #pragma unroll
    for (int i = 1; i < 8; i++) m = fmaxf(m, sh[i]);
    __syncthreads();
    float sum = 0.f;
    #pragma unroll
    for (int i = 0; i < 16; i++) { v[i] = expf(v[i] - m); sum += v[i]; }
    #pragma unroll
    for (int o = 16; o > 0; o >>= 1) sum += __shfl_xor_sync(0xffffffffu, sum, o);
    if ((t & 31) == 0) sh[w] = sum;
    __syncthreads();
    float tot = 0.f;
    #pragma unroll
    for (int i = 0; i < 8; i++) tot += sh[i];
    float inv = 1.0f / tot;
    #pragma unroll
    for (int i = 0; i < 16; i++) S[t + i * 256] = v[i] * inv;
}

// ---------------- k5: out[b][d][n] = relu(sum_c W[c][d] * M[b][c][n]) ----------------
// 64 d x 128 n tile, BK=16 over c. Output layout == [B, OUT_DIM, H, W] directly.
__global__ void __launch_bounds__(256) k5_output(const float* __restrict__ W,
                                                 float* __restrict__ out) {
    __shared__ float sW[16][64];
    __shared__ float sM[16][128];

    int b  = blockIdx.z;
    int n0 = blockIdx.x * 128;
    int d0 = blockIdx.y * 64;
    const float* Mb = g_M + (size_t)b * DIM * HW;
    float* Ob = out + (size_t)b * DIM * HW;

    int tid = threadIdx.x;
    int tx = tid & 15, ty = tid >> 4;

    float acc[4][8];
    #pragma unroll
    for (int u = 0; u < 4; u++)
        #pragma unroll
        for (int v = 0; v < 8; v++) acc[u][v] = 0.f;

    for (int c0 = 0; c0 < DIM; c0 += 16) {
        #pragma unroll
        for (int t = 0; t < 4; t++) {
            int l = tid + t * 256;
            int cc = l >> 6, dd = l & 63;
            sW[cc][dd] = W[(size_t)(c0 + cc) * DIM + d0 + dd];
        }
        #pragma unroll
        for (int t = 0; t < 8; t++) {
            int l = tid + t * 256;
            int cc = l >> 7, nn = l & 127;
            sM[cc][nn] = Mb[(size_t)(c0 + cc) * HW + n0 + nn];
        }
        __syncthreads();
        #pragma unroll
        for (int kk = 0; kk < 16; kk++) {
            float a[4], bb[8];
            #pragma unroll
            for (int u = 0; u < 4; u++) a[u] = sW[kk][ty * 4 + u];
            #pragma unroll
            for (int v = 0; v < 8; v++) bb[v] = sM[kk][tx * 8 + v];
            #pragma unroll
            for (int u = 0; u < 4; u++)
                #pragma unroll
                for (int v = 0; v < 8; v++) acc[u][v] += a[u] * bb[v];
        }
        __syncthreads();
    }
    #pragma unroll
    for (int u = 0; u < 4; u++) {
        float* orow = Ob + (size_t)(d0 + ty * 4 + u) * HW + n0 + tx * 8;
        #pragma unroll
        for (int v = 0; v < 8; v++) orow[v] = fmaxf(acc[u][v], 0.f);
    }
}

// ---------------- launch ----------------
extern "C" void kernel_launch(void* const* d_in, const int* in_sizes, int n_in,
                              void* d_out, int out_size) {
    const float* feat   = (const float*)d_in[0];   // [8, 512, 64, 64]
    const float* phi_w  = (const float*)d_in[1];   // [256, 512]
    const float* theta_w= (const float*)d_in[2];   // [256, 512]
    const float* weight = (const float*)d_in[3];   // [512, 512]
    float* out = (float*)d_out;                    // [8, 512, 64, 64]

    k1_project<<<dim3(HW / 64, IDIM / 64, BATCH), 256>>>(feat, phi_w, theta_w);
    k1b_normalize<<<BATCH * HW, 256>>>();
    k2_scores<<<dim3(HW / 128, HW / 128, BATCH), 256>>>();
    k3_softmax<<<BATCH * HW, 256>>>();
    k4_aggregate<<<dim3(HW / 128, DIM / 128, BATCH), 256>>>(feat);
    k5_output<<<dim3(HW / 128, DIM / 64, BATCH), 256>>>(weight, out);
}

// round 4
// speedup vs baseline: 1.7916x; 1.7916x over previous
#include <cuda_runtime.h>
#include <cuda_bf16.h>
#include <cstdint>
#include <math.h>

#define BATCH 8
#define DIM   512
#define HW    4096
#define IDIM  256

typedef __nv_bfloat16 bf16;

// ---------------- device scratch (static) ----------------
__device__ float g_S[(size_t)BATCH * HW * HW];       // scores fp32 (512 MB)
__device__ float g_Q[(size_t)BATCH * HW * IDIM];     // phi fp32
__device__ float g_K[(size_t)BATCH * HW * IDIM];     // theta fp32
__device__ bf16  g_Sh[(size_t)BATCH * HW * HW];      // softmax hi/lo planes
__device__ bf16  g_Sl[(size_t)BATCH * HW * HW];
__device__ bf16  g_Fth[(size_t)BATCH * HW * DIM];    // F^T [b][n][c]
__device__ bf16  g_Ftl[(size_t)BATCH * HW * DIM];
__device__ bf16  g_Fh[(size_t)BATCH * DIM * HW];     // F [b][c][m]
__device__ bf16  g_Fl[(size_t)BATCH * DIM * HW];
__device__ bf16  g_Qh[(size_t)BATCH * HW * IDIM];
__device__ bf16  g_Ql[(size_t)BATCH * HW * IDIM];
__device__ bf16  g_Kh[(size_t)BATCH * HW * IDIM];
__device__ bf16  g_Kl[(size_t)BATCH * HW * IDIM];
__device__ bf16  g_Mh[(size_t)BATCH * HW * DIM];     // attn out [b][n][c]
__device__ bf16  g_Ml[(size_t)BATCH * HW * DIM];
__device__ bf16  g_Wth[(size_t)DIM * DIM];           // W^T [d][c]
__device__ bf16  g_Wtl[(size_t)DIM * DIM];
__device__ bf16  g_Pwh[(size_t)IDIM * DIM];
__device__ bf16  g_Pwl[(size_t)IDIM * DIM];
__device__ bf16  g_Twh[(size_t)IDIM * DIM];
__device__ bf16  g_Twl[(size_t)IDIM * DIM];

// ---------------- helpers ----------------
__device__ __forceinline__ uint32_t smem_u32(const void* p) {
    uint32_t a;
    asm("{ .reg .u64 t; cvta.to.shared.u64 t, %1; cvt.u32.u64 %0, t; }" : "=r"(a) : "l"(p));
    return a;
}
__device__ __forceinline__ void cp16(uint32_t d, const void* s) {
    asm volatile("cp.async.cg.shared.global [%0], [%1], 16;" :: "r"(d), "l"(s));
}
__device__ __forceinline__ uint32_t lds32(uint32_t a) {
    uint32_t v;
    asm volatile("ld.shared.b32 %0, [%1];" : "=r"(v) : "r"(a));
    return v;
}
__device__ __forceinline__ void split2(float x, bf16& h, bf16& l) {
    h = __float2bfloat16_rn(x);
    l = __float2bfloat16_rn(x - __bfloat162float(h));
}

#define MMA_BF16(c, a, b)                                                        \
    asm volatile(                                                                \
        "mma.sync.aligned.m16n8k16.row.col.f32.bf16.bf16.f32 "                   \
        "{%0,%1,%2,%3}, {%4,%5,%6,%7}, {%8,%9}, {%0,%1,%2,%3};"                  \
        : "+f"((c)[0]), "+f"((c)[1]), "+f"((c)[2]), "+f"((c)[3])                 \
        : "r"((a)[0]), "r"((a)[1]), "r"((a)[2]), "r"((a)[3]),                    \
          "r"((b)[0]), "r"((b)[1]))

// swizzled smem byte offset: row (0..127) * 64B, 16 words of 4B per row,
// 16B granule g placed at g ^ ((row>>1)&3)  -> conflict-free frag reads
__device__ __forceinline__ int soff(int row, int word) {
    return row * 64 + ((((word >> 2) ^ ((row >> 1) & 3)) & 3) << 4) + ((word & 3) << 2);
}

__device__ __forceinline__ void fill_pl(uint32_t dbase, const bf16* src, int Kdim, int tid) {
    #pragma unroll
    for (int t = 0; t < 2; t++) {
        int idx = tid + t * 256;
        int row = idx >> 2, q = idx & 3;
        cp16(dbase + row * 64 + ((q ^ ((row >> 1) & 3)) << 4),
             src + (size_t)row * Kdim + q * 8);
    }
}

// ================= bf16-split NT GEMM via mma.sync =================
// C[m][n] = sum_k A[m][k]*B[n][k], A=Ah+Al, B=Bh+Bl (lo*lo dropped).
// CTA 128x128, 8 warps of 64x32, BK=32, cp.async double buffer.
// mode 0: fp32 store   1: relu fp32 store   2: bf16 hi/lo split store
__global__ void __launch_bounds__(256) gemm_bf16(
    const bf16* __restrict__ Ah, const bf16* __restrict__ Al,
    const bf16* __restrict__ Bh, const bf16* __restrict__ Bl,
    float* __restrict__ C, bf16* __restrict__ Ch, bf16* __restrict__ Cl,
    int Kdim, int Ncols, size_t sA, size_t sB, size_t sC, int mode)
{
    extern __shared__ char smem[];
    const int tid  = threadIdx.x;
    const int lane = tid & 31, wid = tid >> 5;
    const int g = lane >> 2, tg = lane & 3;
    const int wm = wid >> 2, wn = wid & 3;
    const uint32_t sb = smem_u32(smem);

    const size_t aoff = blockIdx.z * sA + (size_t)blockIdx.y * 128 * Kdim;
    const size_t boff = blockIdx.z * sB + (size_t)blockIdx.x * 128 * Kdim;
    const bf16* pAh = Ah + aoff;
    const bf16* pAl = Al + aoff;
    const bf16* pBh = Bh + boff;
    const bf16* pBl = Bl + boff;

    float acc[4][4][4];
    #pragma unroll
    for (int i = 0; i < 4; i++)
        #pragma unroll
        for (int j = 0; j < 4; j++)
            #pragma unroll
            for (int e = 0; e < 4; e++) acc[i][j][e] = 0.f;

    const int NC = Kdim >> 5;

    fill_pl(sb +     0, pAh, Kdim, tid);
    fill_pl(sb +  8192, pAl, Kdim, tid);
    fill_pl(sb + 16384, pBh, Kdim, tid);
    fill_pl(sb + 24576, pBl, Kdim, tid);
    asm volatile("cp.async.commit_group;");

    for (int c = 0; c < NC; c++) {
        if (c + 1 < NC) {
            uint32_t nb = sb + ((c + 1) & 1) * 32768;
            int ko = (c + 1) * 32;
            fill_pl(nb +     0, pAh + ko, Kdim, tid);
            fill_pl(nb +  8192, pAl + ko, Kdim, tid);
            fill_pl(nb + 16384, pBh + ko, Kdim, tid);
            fill_pl(nb + 24576, pBl + ko, Kdim, tid);
            asm volatile("cp.async.commit_group;");
            asm volatile("cp.async.wait_group 1;");
        } else {
            asm volatile("cp.async.wait_group 0;");
        }
        __syncthreads();

        uint32_t bb = sb + (c & 1) * 32768;
        #pragma unroll
        for (int s = 0; s < 2; s++) {
            const int wa = tg + 8 * s;
            uint32_t bhf[4][2], blf[4][2];
            #pragma unroll
            for (int j = 0; j < 4; j++) {
                int rB = wn * 32 + j * 8 + g;
                bhf[j][0] = lds32(bb + 16384 + soff(rB, wa));
                bhf[j][1] = lds32(bb + 16384 + soff(rB, wa + 4));
                blf[j][0] = lds32(bb + 24576 + soff(rB, wa));
                blf[j][1] = lds32(bb + 24576 + soff(rB, wa + 4));
            }
            #pragma unroll
            for (int i = 0; i < 4; i++) {
                int rA = wm * 64 + i * 16 + g;
                uint32_t ahf[4], alf[4];
                ahf[0] = lds32(bb + soff(rA,     wa));
                ahf[1] = lds32(bb + soff(rA + 8, wa));
                ahf[2] = lds32(bb + soff(rA,     wa + 4));
                ahf[3] = lds32(bb + soff(rA + 8, wa + 4));
                alf[0] = lds32(bb + 8192 + soff(rA,     wa));
                alf[1] = lds32(bb + 8192 + soff(rA + 8, wa));
                alf[2] = lds32(bb + 8192 + soff(rA,     wa + 4));
                alf[3] = lds32(bb + 8192 + soff(rA + 8, wa + 4));
                #pragma unroll
                for (int j = 0; j < 4; j++) {
                    MMA_BF16(acc[i][j], ahf, bhf[j]);
                    MMA_BF16(acc[i][j], ahf, blf[j]);
                    MMA_BF16(acc[i][j], alf, bhf[j]);
                }
            }
        }
        __syncthreads();
    }

    // epilogue
    const int row0 = blockIdx.y * 128 + wm * 64;
    const int col0 = blockIdx.x * 128 + wn * 32;
    #pragma unroll
    for (int i = 0; i < 4; i++) {
        #pragma unroll
        for (int j = 0; j < 4; j++) {
            int r  = row0 + i * 16 + g;
            int cc = col0 + j * 8 + tg * 2;
            if (mode == 2) {
                size_t o0 = blockIdx.z * sC + (size_t)r * Ncols + cc;
                size_t o1 = o0 + 8 * (size_t)Ncols;
                bf16 h0, l0, h1, l1;
                __nv_bfloat162 hh, ll;
                split2(acc[i][j][0], h0, l0); split2(acc[i][j][1], h1, l1);
                hh.x = h0; hh.y = h1; ll.x = l0; ll.y = l1;
                *reinterpret_cast<__nv_bfloat162*>(Ch + o0) = hh;
                *reinterpret_cast<__nv_bfloat162*>(Cl + o0) = ll;
                split2(acc[i][j][2], h0, l0); split2(acc[i][j][3], h1, l1);
                hh.x = h0; hh.y = h1; ll.x = l0; ll.y = l1;
                *reinterpret_cast<__nv_bfloat162*>(Ch + o1) = hh;
                *reinterpret_cast<__nv_bfloat162*>(Cl + o1) = ll;
            } else {
                float* b0 = C + blockIdx.z * sC + (size_t)r * Ncols + cc;
                float* b1 = b0 + 8 * (size_t)Ncols;
                float2 v0, v1;
                v0.x = acc[i][j][0]; v0.y = acc[i][j][1];
                v1.x = acc[i][j][2]; v1.y = acc[i][j][3];
                if (mode == 1) {
                    v0.x = fmaxf(v0.x, 0.f); v0.y = fmaxf(v0.y, 0.f);
                    v1.x = fmaxf(v1.x, 0.f); v1.y = fmaxf(v1.y, 0.f);
                }
                *reinterpret_cast<float2*>(b0) = v0;
                *reinterpret_cast<float2*>(b1) = v1;
            }
        }
    }
}

// ---------------- transpose + bf16 split: out[col][row] = in[row][col] ----------------
__global__ void __launch_bounds__(256) trans_conv(const float* __restrict__ in,
                                                  bf16* __restrict__ oh, bf16* __restrict__ ol,
                                                  int R, int C) {
    __shared__ float t[32][33];
    int b = blockIdx.z;
    const float* ib = in + (size_t)b * R * C;
    size_t ob = (size_t)b * R * C;
    int c0 = blockIdx.x * 32, r0 = blockIdx.y * 32;
    int x = threadIdx.x, y = threadIdx.y;
    #pragma unroll
    for (int i = 0; i < 32; i += 8)
        t[y + i][x] = ib[(size_t)(r0 + y + i) * C + c0 + x];
    __syncthreads();
    #pragma unroll
    for (int i = 0; i < 32; i += 8) {
        float v = t[x][y + i];
        bf16 h, l; split2(v, h, l);
        size_t o = ob + (size_t)(c0 + y + i) * R + r0 + x;
        oh[o] = h; ol[o] = l;
    }
}

// ---------------- elementwise bf16 split ----------------
__global__ void __launch_bounds__(256) conv_split(const float* __restrict__ in,
                                                  bf16* __restrict__ oh, bf16* __restrict__ ol) {
    size_t i0 = ((size_t)blockIdx.x * 256 + threadIdx.x) * 4;
    float4 v = *reinterpret_cast<const float4*>(in + i0);
    bf16 h0, l0, h1, l1;
    __nv_bfloat162 hh, ll;
    split2(v.x, h0, l0); split2(v.y, h1, l1);
    hh.x = h0; hh.y = h1; ll.x = l0; ll.y = l1;
    *reinterpret_cast<__nv_bfloat162*>(oh + i0) = hh;
    *reinterpret_cast<__nv_bfloat162*>(ol + i0) = ll;
    split2(v.z, h0, l0); split2(v.w, h1, l1);
    hh.x = h0; hh.y = h1; ll.x = l0; ll.y = l1;
    *reinterpret_cast<__nv_bfloat162*>(oh + i0 + 2) = hh;
    *reinterpret_cast<__nv_bfloat162*>(ol + i0 + 2) = ll;
}

// ---------------- normalize Q,K rows + split to bf16 planes ----------------
__global__ void __launch_bounds__(256) k1b_normalize() {
    size_t row = blockIdx.x;
    const float* q = g_Q + row * IDIM;
    const float* k = g_K + row * IDIM;
    int t = threadIdx.x;
    float qv = q[t], kv = k[t];
    float sq = qv * qv, sk = kv * kv;
    #pragma unroll
    for (int o = 16; o > 0; o >>= 1) {
        sq += __shfl_xor_sync(0xffffffffu, sq, o);
        sk += __shfl_xor_sync(0xffffffffu, sk, o);
    }
    __shared__ float sh[16];
    int w = t >> 5;
    if ((t & 31) == 0) { sh[w] = sq; sh[8 + w] = sk; }
    __syncthreads();
    float tq = 0.f, tk = 0.f;
    #pragma unroll
    for (int i = 0; i < 8; i++) { tq += sh[i]; tk += sh[8 + i]; }
    float qn = qv * rsqrtf(tq) * sqrtf(tq) / tq; // avoid: use direct
    qn = qv / sqrtf(tq);
    float kn = kv / sqrtf(tk);
    bf16 h, l;
    size_t o = row * IDIM + t;
    split2(qn, h, l); g_Qh[o] = h; g_Ql[o] = l;
    split2(kn, h, l); g_Kh[o] = h; g_Kl[o] = l;
}

// ---------------- softmax + split to bf16 planes ----------------
__global__ void __launch_bounds__(256) k3_softmax() {
    size_t row = blockIdx.x;
    const float* S = g_S + row * (size_t)HW;
    bf16* Sh = g_Sh + row * (size_t)HW;
    bf16* Sl = g_Sl + row * (size_t)HW;
    int t = threadIdx.x;
    float v[16];
    float mx = -3.0e38f;
    #pragma unroll
    for (int i = 0; i < 16; i++) { v[i] = S[t + i * 256]; mx = fmaxf(mx, v[i]); }
    #pragma unroll
    for (int o = 16; o > 0; o >>= 1) mx = fmaxf(mx, __shfl_xor_sync(0xffffffffu, mx, o));
    __shared__ float sh[8];
    int w = t >> 5;
    if ((t & 31) == 0) sh[w] = mx;
    __syncthreads();
    float m = sh[0];
    #pragma unroll
    for (int i = 1; i < 8; i++) m = fmaxf(m, sh[i]);
    __syncthreads();
    float sum = 0.f;
    #pragma unroll
    for (int i = 0; i < 16; i++) { v[i] = expf(v[i] - m); sum += v[i]; }
    #pragma unroll
    for (int o = 16; o > 0; o >>= 1) sum += __shfl_xor_sync(0xffffffffu, sum, o);
    if ((t & 31) == 0) sh[w] = sum;
    __syncthreads();
    float tot = 0.f;
    #pragma unroll
    for (int i = 0; i < 8; i++) tot += sh[i];
    float inv = 1.0f / tot;
    #pragma unroll
    for (int i = 0; i < 16; i++) {
        float p = v[i] * inv;
        bf16 h, l; split2(p, h, l);
        Sh[t + i * 256] = h;
        Sl[t + i * 256] = l;
    }
}

// ---------------- launch ----------------
extern "C" void kernel_launch(void* const* d_in, const int* in_sizes, int n_in,
                              void* d_out, int out_size) {
    const float* feat    = (const float*)d_in[0];   // [8, 512, 64, 64]
    const float* phi_w   = (const float*)d_in[1];   // [256, 512]
    const float* theta_w = (const float*)d_in[2];   // [256, 512]
    const float* weight  = (const float*)d_in[3];   // [512, 512]
    float* out = (float*)d_out;                     // [8, 512, 64, 64]

    cudaFuncSetAttribute(gemm_bf16, cudaFuncAttributeMaxDynamicSharedMemorySize, 65536);

    float *S, *Q, *Kf;
    bf16 *Sh, *Sl, *Fth, *Ftl, *Fh, *Fl, *Qh, *Ql, *Kh, *Kl, *Mh, *Ml;
    bf16 *Wth, *Wtl, *Pwh, *Pwl, *Twh, *Twl;
    cudaGetSymbolAddress((void**)&S,   g_S);
    cudaGetSymbolAddress((void**)&Q,   g_Q);
    cudaGetSymbolAddress((void**)&Kf,  g_K);
    cudaGetSymbolAddress((void**)&Sh,  g_Sh);
    cudaGetSymbolAddress((void**)&Sl,  g_Sl);
    cudaGetSymbolAddress((void**)&Fth, g_Fth);
    cudaGetSymbolAddress((void**)&Ftl, g_Ftl);
    cudaGetSymbolAddress((void**)&Fh,  g_Fh);
    cudaGetSymbolAddress((void**)&Fl,  g_Fl);
    cudaGetSymbolAddress((void**)&Qh,  g_Qh);
    cudaGetSymbolAddress((void**)&Ql,  g_Ql);
    cudaGetSymbolAddress((void**)&Kh,  g_Kh);
    cudaGetSymbolAddress((void**)&Kl,  g_Kl);
    cudaGetSymbolAddress((void**)&Mh,  g_Mh);
    cudaGetSymbolAddress((void**)&Ml,  g_Ml);
    cudaGetSymbolAddress((void**)&Wth, g_Wth);
    cudaGetSymbolAddress((void**)&Wtl, g_Wtl);
    cudaGetSymbolAddress((void**)&Pwh, g_Pwh);
    cudaGetSymbolAddress((void**)&Pwl, g_Pwl);
    cudaGetSymbolAddress((void**)&Twh, g_Twh);
    cudaGetSymbolAddress((void**)&Twl, g_Twl);

    // prep: transposes + bf16 splits
    trans_conv<<<dim3(HW / 32, DIM / 32, BATCH), dim3(32, 8)>>>(feat, Fth, Ftl, DIM, HW);
    trans_conv<<<dim3(DIM / 32, DIM / 32, 1), dim3(32, 8)>>>(weight, Wth, Wtl, DIM, DIM);
    conv_split<<<(BATCH * DIM * HW) / 1024, 256>>>(feat, Fh, Fl);
    conv_split<<<(IDIM * DIM) / 1024, 256>>>(phi_w, Pwh, Pwl);
    conv_split<<<(IDIM * DIM) / 1024, 256>>>(theta_w, Twh, Twl);

    // k1: Q[n][i] = Ft[n][:] . phi_w[i][:]   (M=4096, N=256, K=512)
    gemm_bf16<<<dim3(IDIM / 128, HW / 128, BATCH), 256, 65536>>>(
        Fth, Ftl, Pwh, Pwl, Q, nullptr, nullptr,
        DIM, IDIM, (size_t)HW * DIM, 0, (size_t)HW * IDIM, 0);
    gemm_bf16<<<dim3(IDIM / 128, HW / 128, BATCH), 256, 65536>>>(
        Fth, Ftl, Twh, Twl, Kf, nullptr, nullptr,
        DIM, IDIM, (size_t)HW * DIM, 0, (size_t)HW * IDIM, 0);

    k1b_normalize<<<BATCH * HW, 256>>>();

    // k2: S[n][m] = Qn . Km   (M=N=4096, K=256)
    gemm_bf16<<<dim3(HW / 128, HW / 128, BATCH), 256, 65536>>>(
        Qh, Ql, Kh, Kl, S, nullptr, nullptr,
        IDIM, HW, (size_t)HW * IDIM, (size_t)HW * IDIM, (size_t)HW * HW, 0);

    k3_softmax<<<BATCH * HW, 256>>>();

    // k4: M[n][c] = sum_m S[n][m] * F[c][m]   (M=4096, N=512, K=4096) -> bf16 planes
    gemm_bf16<<<dim3(DIM / 128, HW / 128, BATCH), 256, 65536>>>(
        Sh, Sl, Fh, Fl, nullptr, Mh, Ml,
        HW, DIM, (size_t)HW * HW, (size_t)DIM * HW, (size_t)HW * DIM, 2);

    // k5: out[d][n] = relu(Wt[d][:] . M[n][:])   (M=512, N=4096, K=512)
    gemm_bf16<<<dim3(HW / 128, DIM / 128, BATCH), 256, 65536>>>(
        Wth, Wtl, Mh, Ml, out, nullptr, nullptr,
        DIM, HW, 0, (size_t)HW * DIM, (size_t)DIM * HW, 1);
}

// round 5
// speedup vs baseline: 2.7755x; 1.5492x over previous
#include <cuda_runtime.h>
#include <cuda_bf16.h>
#include <cstdint>
#include <math.h>

#define BATCH 8
#define DIM   512
#define HW    4096
#define IDIM  256

typedef __nv_bfloat16 bf16;

// ---------------- device scratch (static) ----------------
__device__ float g_Q[(size_t)BATCH * HW * IDIM];     // phi fp32
__device__ float g_K[(size_t)BATCH * HW * IDIM];     // theta fp32
__device__ bf16  g_Eh[(size_t)BATCH * HW * HW];      // exp(scores) hi/lo planes
__device__ bf16  g_El[(size_t)BATCH * HW * HW];
__device__ float g_part[(size_t)BATCH * HW * 32];    // per-CTA row partial sums
__device__ float g_inv[(size_t)BATCH * HW];          // 1 / rowsum
__device__ bf16  g_Fth[(size_t)BATCH * HW * DIM];    // F^T [b][n][c]
__device__ bf16  g_Ftl[(size_t)BATCH * HW * DIM];
__device__ bf16  g_Fh[(size_t)BATCH * DIM * HW];     // F [b][c][m]
__device__ bf16  g_Fl[(size_t)BATCH * DIM * HW];
__device__ bf16  g_Qh[(size_t)BATCH * HW * IDIM];
__device__ bf16  g_Ql[(size_t)BATCH * HW * IDIM];
__device__ bf16  g_Kh[(size_t)BATCH * HW * IDIM];
__device__ bf16  g_Kl[(size_t)BATCH * HW * IDIM];
__device__ bf16  g_Mh[(size_t)BATCH * HW * DIM];     // attn out [b][n][c]
__device__ bf16  g_Ml[(size_t)BATCH * HW * DIM];
__device__ bf16  g_Wth[(size_t)DIM * DIM];           // W^T [d][c]
__device__ bf16  g_Wtl[(size_t)DIM * DIM];
__device__ bf16  g_Pwh[(size_t)IDIM * DIM];
__device__ bf16  g_Pwl[(size_t)IDIM * DIM];
__device__ bf16  g_Twh[(size_t)IDIM * DIM];
__device__ bf16  g_Twl[(size_t)IDIM * DIM];

// ---------------- helpers ----------------
__device__ __forceinline__ uint32_t smem_u32(const void* p) {
    uint32_t a;
    asm("{ .reg .u64 t; cvta.to.shared.u64 t, %1; cvt.u32.u64 %0, t; }" : "=r"(a) : "l"(p));
    return a;
}
__device__ __forceinline__ void cp16(uint32_t d, const void* s) {
    asm volatile("cp.async.cg.shared.global [%0], [%1], 16;" :: "r"(d), "l"(s));
}
__device__ __forceinline__ void split2(float x, bf16& h, bf16& l) {
    h = __float2bfloat16_rn(x);
    l = __float2bfloat16_rn(x - __bfloat162float(h));
}

#define LDSM4(R, addr)                                                           \
    asm volatile("ldmatrix.sync.aligned.m8n8.x4.shared.b16 {%0,%1,%2,%3}, [%4];" \
        : "=r"((R)[0]), "=r"((R)[1]), "=r"((R)[2]), "=r"((R)[3]) : "r"(addr))

#define MMA_BF16(c, a, b0, b1)                                                   \
    asm volatile(                                                                \
        "mma.sync.aligned.m16n8k16.row.col.f32.bf16.bf16.f32 "                   \
        "{%0,%1,%2,%3}, {%4,%5,%6,%7}, {%8,%9}, {%0,%1,%2,%3};"                  \
        : "+f"((c)[0]), "+f"((c)[1]), "+f"((c)[2]), "+f"((c)[3])                 \
        : "r"((a)[0]), "r"((a)[1]), "r"((a)[2]), "r"((a)[3]),                    \
          "r"((b0)), "r"((b1)))

// 16B granule g of row r lives at g ^ ((r>>1)&3)  (64B rows, conflict-free)
__device__ __forceinline__ void fill_pl(uint32_t dbase, const bf16* src, int Kdim, int tid) {
    #pragma unroll
    for (int t = 0; t < 2; t++) {
        int idx = tid + t * 256;
        int row = idx >> 2, q = idx & 3;
        cp16(dbase + row * 64 + ((q ^ ((row >> 1) & 3)) << 4),
             src + (size_t)row * Kdim + q * 8);
    }
}

// ================= bf16-split NT GEMM via mma.sync + ldmatrix =================
// C[m][n] = sum_k A[m][k]*B[n][k], A=Ah+Al, B=Bh+Bl (lo*lo dropped).
// CTA 128x128, 8 warps (2x4) of 64x32, BK=32, cp.async double buffer.
// mode 0: fp32 store   1: relu fp32 store
// mode 3: exp() + bf16 split store + row partial sums (k2/scores)
// mode 4: row scale by Inv + bf16 split store (k4/aggregate)
__global__ void __launch_bounds__(256) gemm_bf16(
    const bf16* __restrict__ Ah, const bf16* __restrict__ Al,
    const bf16* __restrict__ Bh, const bf16* __restrict__ Bl,
    float* __restrict__ C, bf16* __restrict__ Ch, bf16* __restrict__ Cl,
    float* __restrict__ Part, const float* __restrict__ Inv,
    int Kdim, int Ncols, size_t sA, size_t sB, size_t sC, int mode)
{
    extern __shared__ char smem[];
    const int tid  = threadIdx.x;
    const int lane = tid & 31, wid = tid >> 5;
    const int g = lane >> 2, tg = lane & 3;
    const int wm = wid >> 2, wn = wid & 3;
    const uint32_t sb = smem_u32(smem);

    const size_t aoff = blockIdx.z * sA + (size_t)blockIdx.y * 128 * Kdim;
    const size_t boff = blockIdx.z * sB + (size_t)blockIdx.x * 128 * Kdim;
    const bf16* pAh = Ah + aoff;
    const bf16* pAl = Al + aoff;
    const bf16* pBh = Bh + boff;
    const bf16* pBl = Bl + boff;

    float acc[4][4][4];
    #pragma unroll
    for (int i = 0; i < 4; i++)
        #pragma unroll
        for (int j = 0; j < 4; j++)
            #pragma unroll
            for (int e = 0; e < 4; e++) acc[i][j][e] = 0.f;

    const int NC = Kdim >> 5;
    const int rb = lane & 15, gs = lane >> 4;
    const int swz = (rb >> 1) & 3;

    fill_pl(sb +     0, pAh, Kdim, tid);
    fill_pl(sb +  8192, pAl, Kdim, tid);
    fill_pl(sb + 16384, pBh, Kdim, tid);
    fill_pl(sb + 24576, pBl, Kdim, tid);
    asm volatile("cp.async.commit_group;");

    for (int c = 0; c < NC; c++) {
        if (c + 1 < NC) {
            uint32_t nb = sb + ((c + 1) & 1) * 32768;
            int ko = (c + 1) * 32;
            fill_pl(nb +     0, pAh + ko, Kdim, tid);
            fill_pl(nb +  8192, pAl + ko, Kdim, tid);
            fill_pl(nb + 16384, pBh + ko, Kdim, tid);
            fill_pl(nb + 24576, pBl + ko, Kdim, tid);
            asm volatile("cp.async.commit_group;");
            asm volatile("cp.async.wait_group 1;");
        } else {
            asm volatile("cp.async.wait_group 0;");
        }
        __syncthreads();

        uint32_t bb = sb + (c & 1) * 32768;
        #pragma unroll
        for (int s = 0; s < 2; s++) {
            const int gp = (((2 * s + gs) ^ swz) << 4);
            uint32_t ah[4][4], al[4][4], bh[2][4], bl[2][4];
            #pragma unroll
            for (int i = 0; i < 4; i++) {
                uint32_t ra = bb + (uint32_t)(wm * 64 + i * 16 + rb) * 64 + gp;
                LDSM4(ah[i], ra);
                LDSM4(al[i], ra + 8192);
            }
            #pragma unroll
            for (int t = 0; t < 2; t++) {
                uint32_t rbad = bb + 16384 + (uint32_t)(wn * 32 + t * 16 + rb) * 64 + gp;
                LDSM4(bh[t], rbad);
                LDSM4(bl[t], rbad + 8192);
            }
            #pragma unroll
            for (int i = 0; i < 4; i++)
                #pragma unroll
                for (int j = 0; j < 4; j++) {
                    const int t = j >> 1, u = j & 1;
                    MMA_BF16(acc[i][j], ah[i], bh[t][u], bh[t][u + 2]);
                    MMA_BF16(acc[i][j], ah[i], bl[t][u], bl[t][u + 2]);
                    MMA_BF16(acc[i][j], al[i], bh[t][u], bh[t][u + 2]);
                }
        }
        __syncthreads();
    }

    // ---------------- epilogue ----------------
    const int row0 = blockIdx.y * 128 + wm * 64;
    const int col0 = blockIdx.x * 128 + wn * 32;
    const int bz = blockIdx.z;

    if (mode == 3) {
        float* spart = (float*)smem;   // [128][4]
        float rsum[4][2];
        #pragma unroll
        for (int i = 0; i < 4; i++) { rsum[i][0] = 0.f; rsum[i][1] = 0.f; }
        #pragma unroll
        for (int i = 0; i < 4; i++) {
            int r0 = row0 + i * 16 + g;
            #pragma unroll
            for (int j = 0; j < 4; j++) {
                int cc = col0 + j * 8 + tg * 2;
                float e0 = __expf(acc[i][j][0]);
                float e1 = __expf(acc[i][j][1]);
                float e2 = __expf(acc[i][j][2]);
                float e3 = __expf(acc[i][j][3]);
                rsum[i][0] += e0 + e1;
                rsum[i][1] += e2 + e3;
                size_t o0 = bz * sC + (size_t)r0 * Ncols + cc;
                size_t o1 = o0 + 8 * (size_t)Ncols;
                bf16 h0, l0, h1, l1;
                __nv_bfloat162 hh, ll;
                split2(e0, h0, l0); split2(e1, h1, l1);
                hh.x = h0; hh.y = h1; ll.x = l0; ll.y = l1;
                *reinterpret_cast<__nv_bfloat162*>(Ch + o0) = hh;
                *reinterpret_cast<__nv_bfloat162*>(Cl + o0) = ll;
                split2(e2, h0, l0); split2(e3, h1, l1);
                hh.x = h0; hh.y = h1; ll.x = l0; ll.y = l1;
                *reinterpret_cast<__nv_bfloat162*>(Ch + o1) = hh;
                *reinterpret_cast<__nv_bfloat162*>(Cl + o1) = ll;
            }
        }
        // reduce partial row sums across tg lanes, then across the 4 wn warps
        #pragma unroll
        for (int i = 0; i < 4; i++) {
            #pragma unroll
            for (int h = 0; h < 2; h++) {
                float v = rsum[i][h];
                v += __shfl_xor_sync(0xffffffffu, v, 1);
                v += __shfl_xor_sync(0xffffffffu, v, 2);
                if (tg == 0)
                    spart[(wm * 64 + i * 16 + g + h * 8) * 4 + wn] = v;
            }
        }
        __syncthreads();
        if (tid < 128) {
            float4 p = *reinterpret_cast<float4*>(spart + tid * 4);
            Part[((size_t)bz * HW + blockIdx.y * 128 + tid) * 32 + blockIdx.x] =
                p.x + p.y + p.z + p.w;
        }
        return;
    }

    #pragma unroll
    for (int i = 0; i < 4; i++) {
        int r0 = row0 + i * 16 + g;
        float inv0 = 1.f, inv1 = 1.f;
        if (mode == 4) {
            inv0 = Inv[(size_t)bz * HW + r0];
            inv1 = Inv[(size_t)bz * HW + r0 + 8];
        }
        #pragma unroll
        for (int j = 0; j < 4; j++) {
            int cc = col0 + j * 8 + tg * 2;
            if (mode == 4) {
                size_t o0 = bz * sC + (size_t)r0 * Ncols + cc;
                size_t o1 = o0 + 8 * (size_t)Ncols;
                bf16 h0, l0, h1, l1;
                __nv_bfloat162 hh, ll;
                split2(acc[i][j][0] * inv0, h0, l0);
                split2(acc[i][j][1] * inv0, h1, l1);
                hh.x = h0; hh.y = h1; ll.x = l0; ll.y = l1;
                *reinterpret_cast<__nv_bfloat162*>(Ch + o0) = hh;
                *reinterpret_cast<__nv_bfloat162*>(Cl + o0) = ll;
                split2(acc[i][j][2] * inv1, h0, l0);
                split2(acc[i][j][3] * inv1, h1, l1);
                hh.x = h0; hh.y = h1; ll.x = l0; ll.y = l1;
                *reinterpret_cast<__nv_bfloat162*>(Ch + o1) = hh;
                *reinterpret_cast<__nv_bfloat162*>(Cl + o1) = ll;
            } else {
                float* b0 = C + bz * sC + (size_t)r0 * Ncols + cc;
                float* b1 = b0 + 8 * (size_t)Ncols;
                float2 v0, v1;
                v0.x = acc[i][j][0]; v0.y = acc[i][j][1];
                v1.x = acc[i][j][2]; v1.y = acc[i][j][3];
                if (mode == 1) {
                    v0.x = fmaxf(v0.x, 0.f); v0.y = fmaxf(v0.y, 0.f);
                    v1.x = fmaxf(v1.x, 0.f); v1.y = fmaxf(v1.y, 0.f);
                }
                *reinterpret_cast<float2*>(b0) = v0;
                *reinterpret_cast<float2*>(b1) = v1;
            }
        }
    }
}

// ---------------- inv rowsum: 1 / sum of 32 partials ----------------
__global__ void __launch_bounds__(256) k3b_inv() {
    int wid = threadIdx.x >> 5, lane = threadIdx.x & 31;
    size_t rr = (size_t)blockIdx.x * 8 + wid;
    float v = g_part[rr * 32 + lane];
    #pragma unroll
    for (int o = 16; o > 0; o >>= 1) v += __shfl_xor_sync(0xffffffffu, v, o);
    if (lane == 0) g_inv[rr] = 1.0f / v;
}

// ---------------- transpose + bf16 split ----------------
__global__ void __launch_bounds__(256) trans_conv(const float* __restrict__ in,
                                                  bf16* __restrict__ oh, bf16* __restrict__ ol,
                                                  int R, int C) {
    __shared__ float t[32][33];
    int b = blockIdx.z;
    const float* ib = in + (size_t)b * R * C;
    size_t ob = (size_t)b * R * C;
    int c0 = blockIdx.x * 32, r0 = blockIdx.y * 32;
    int x = threadIdx.x, y = threadIdx.y;
    #pragma unroll
    for (int i = 0; i < 32; i += 8)
        t[y + i][x] = ib[(size_t)(r0 + y + i) * C + c0 + x];
    __syncthreads();
    #pragma unroll
    for (int i = 0; i < 32; i += 8) {
        float v = t[x][y + i];
        bf16 h, l; split2(v, h, l);
        size_t o = ob + (size_t)(c0 + y + i) * R + r0 + x;
        oh[o] = h; ol[o] = l;
    }
}

// ---------------- elementwise bf16 split ----------------
__global__ void __launch_bounds__(256) conv_split(const float* __restrict__ in,
                                                  bf16* __restrict__ oh, bf16* __restrict__ ol) {
    size_t i0 = ((size_t)blockIdx.x * 256 + threadIdx.x) * 4;
    float4 v = *reinterpret_cast<const float4*>(in + i0);
    bf16 h0, l0, h1, l1;
    __nv_bfloat162 hh, ll;
    split2(v.x, h0, l0); split2(v.y, h1, l1);
    hh.x = h0; hh.y = h1; ll.x = l0; ll.y = l1;
    *reinterpret_cast<__nv_bfloat162*>(oh + i0) = hh;
    *reinterpret_cast<__nv_bfloat162*>(ol + i0) = ll;
    split2(v.z, h0, l0); split2(v.w, h1, l1);
    hh.x = h0; hh.y = h1; ll.x = l0; ll.y = l1;
    *reinterpret_cast<__nv_bfloat162*>(oh + i0 + 2) = hh;
    *reinterpret_cast<__nv_bfloat162*>(ol + i0 + 2) = ll;
}

// ---------------- normalize Q,K rows + split to bf16 planes ----------------
__global__ void __launch_bounds__(256) k1b_normalize() {
    size_t row = blockIdx.x;
    const float* q = g_Q + row * IDIM;
    const float* k = g_K + row * IDIM;
    int t = threadIdx.x;
    float qv = q[t], kv = k[t];
    float sq = qv * qv, sk = kv * kv;
    #pragma unroll
    for (int o = 16; o > 0; o >>= 1) {
        sq += __shfl_xor_sync(0xffffffffu, sq, o);
        sk += __shfl_xor_sync(0xffffffffu, sk, o);
    }
    __shared__ float sh[16];
    int w = t >> 5;
    if ((t & 31) == 0) { sh[w] = sq; sh[8 + w] = sk; }
    __syncthreads();
    float tq = 0.f, tk = 0.f;
    #pragma unroll
    for (int i = 0; i < 8; i++) { tq += sh[i]; tk += sh[8 + i]; }
    float qn = qv / sqrtf(tq);
    float kn = kv / sqrtf(tk);
    bf16 h, l;
    size_t o = row * IDIM + t;
    split2(qn, h, l); g_Qh[o] = h; g_Ql[o] = l;
    split2(kn, h, l); g_Kh[o] = h; g_Kl[o] = l;
}

// ---------------- launch ----------------
extern "C" void kernel_launch(void* const* d_in, const int* in_sizes, int n_in,
                              void* d_out, int out_size) {
    const float* feat    = (const float*)d_in[0];   // [8, 512, 64, 64]
    const float* phi_w   = (const float*)d_in[1];   // [256, 512]
    const float* theta_w = (const float*)d_in[2];   // [256, 512]
    const float* weight  = (const float*)d_in[3];   // [512, 512]
    float* out = (float*)d_out;                     // [8, 512, 64, 64]

    cudaFuncSetAttribute(gemm_bf16, cudaFuncAttributeMaxDynamicSharedMemorySize, 65536);

    float *Q, *Kf, *Part, *Inv;
    bf16 *Eh, *El, *Fth, *Ftl, *Fh, *Fl, *Qh, *Ql, *Kh, *Kl, *Mh, *Ml;
    bf16 *Wth, *Wtl, *Pwh, *Pwl, *Twh, *Twl;
    cudaGetSymbolAddress((void**)&Q,    g_Q);
    cudaGetSymbolAddress((void**)&Kf,   g_K);
    cudaGetSymbolAddress((void**)&Part, g_part);
    cudaGetSymbolAddress((void**)&Inv,  g_inv);
    cudaGetSymbolAddress((void**)&Eh,   g_Eh);
    cudaGetSymbolAddress((void**)&El,   g_El);
    cudaGetSymbolAddress((void**)&Fth,  g_Fth);
    cudaGetSymbolAddress((void**)&Ftl,  g_Ftl);
    cudaGetSymbolAddress((void**)&Fh,   g_Fh);
    cudaGetSymbolAddress((void**)&Fl,   g_Fl);
    cudaGetSymbolAddress((void**)&Qh,   g_Qh);
    cudaGetSymbolAddress((void**)&Ql,   g_Ql);
    cudaGetSymbolAddress((void**)&Kh,   g_Kh);
    cudaGetSymbolAddress((void**)&Kl,   g_Kl);
    cudaGetSymbolAddress((void**)&Mh,   g_Mh);
    cudaGetSymbolAddress((void**)&Ml,   g_Ml);
    cudaGetSymbolAddress((void**)&Wth,  g_Wth);
    cudaGetSymbolAddress((void**)&Wtl,  g_Wtl);
    cudaGetSymbolAddress((void**)&Pwh,  g_Pwh);
    cudaGetSymbolAddress((void**)&Pwl,  g_Pwl);
    cudaGetSymbolAddress((void**)&Twh,  g_Twh);
    cudaGetSymbolAddress((void**)&Twl,  g_Twl);

    // prep: transposes + bf16 splits
    trans_conv<<<dim3(HW / 32, DIM / 32, BATCH), dim3(32, 8)>>>(feat, Fth, Ftl, DIM, HW);
    trans_conv<<<dim3(DIM / 32, DIM / 32, 1), dim3(32, 8)>>>(weight, Wth, Wtl, DIM, DIM);
    conv_split<<<(BATCH * DIM * HW) / 1024, 256>>>(feat, Fh, Fl);
    conv_split<<<(IDIM * DIM) / 1024, 256>>>(phi_w, Pwh, Pwl);
    conv_split<<<(IDIM * DIM) / 1024, 256>>>(theta_w, Twh, Twl);

    // k1: Q[n][i] = Ft[n][:] . phi_w[i][:]   (M=4096, N=256, K=512)
    gemm_bf16<<<dim3(IDIM / 128, HW / 128, BATCH), 256, 65536>>>(
        Fth, Ftl, Pwh, Pwl, Q, nullptr, nullptr, nullptr, nullptr,
        DIM, IDIM, (size_t)HW * DIM, 0, (size_t)HW * IDIM, 0);
    gemm_bf16<<<dim3(IDIM / 128, HW / 128, BATCH), 256, 65536>>>(
        Fth, Ftl, Twh, Twl, Kf, nullptr, nullptr, nullptr, nullptr,
        DIM, IDIM, (size_t)HW * DIM, 0, (size_t)HW * IDIM, 0);

    k1b_normalize<<<BATCH * HW, 256>>>();

    // k2: E[n][m] = exp(Qn . Km)  + row partial sums  (M=N=4096, K=256)
    gemm_bf16<<<dim3(HW / 128, HW / 128, BATCH), 256, 65536>>>(
        Qh, Ql, Kh, Kl, nullptr, Eh, El, Part, nullptr,
        IDIM, HW, (size_t)HW * IDIM, (size_t)HW * IDIM, (size_t)HW * HW, 3);

    k3b_inv<<<HW * BATCH / 8, 256>>>();

    // k4: M[n][c] = (sum_m E[n][m] * F[c][m]) * inv[n]  (M=4096, N=512, K=4096)
    gemm_bf16<<<dim3(DIM / 128, HW / 128, BATCH), 256, 65536>>>(
        Eh, El, Fh, Fl, nullptr, Mh, Ml, nullptr, Inv,
        HW, DIM, (size_t)HW * HW, (size_t)DIM * HW, (size_t)HW * DIM, 4);

    // k5: out[d][n] = relu(Wt[d][:] . M[n][:])   (M=512, N=4096, K=512)
    gemm_bf16<<<dim3(HW / 128, DIM / 128, BATCH), 256, 65536>>>(
        Wth, Wtl, Mh, Ml, out, nullptr, nullptr, nullptr, nullptr,
        DIM, HW, 0, (size_t)HW * DIM, (size_t)DIM * HW, 1);
}